// round 2
// baseline (speedup 1.0000x reference)
#include <cuda_runtime.h>

// Problem constants (fixed shapes per reference)
#define NPTS 65536
#define DIM  256
#define KCB  4096

// GEMM tiling
#define BM 128
#define BN 128
#define BK 16
#define TM 8
#define TN 8
#define NTHREADS 256

// Scratch (allocation-free rule: __device__ globals)
__device__ float g_xsq[NPTS];
__device__ float g_csq[KCB];

// ---------------------------------------------------------------------------
// Kernel 1: per-row squared norms for x and codebook. One warp per row.
// ---------------------------------------------------------------------------
__global__ void sqnorm_kernel(const float* __restrict__ x,
                              const float* __restrict__ cb) {
    int warp = (blockIdx.x * blockDim.x + threadIdx.x) >> 5;
    int lane = threadIdx.x & 31;
    const float* src;
    float* dst;
    if (warp < NPTS) {
        src = x + (size_t)warp * DIM;
        dst = g_xsq + warp;
    } else {
        int r = warp - NPTS;
        if (r >= KCB) return;
        src = cb + (size_t)r * DIM;
        dst = g_csq + r;
    }
    float s = 0.f;
#pragma unroll
    for (int i = 0; i < DIM / 32; i++) {
        float v = src[lane + i * 32];
        s = fmaf(v, v, s);
    }
#pragma unroll
    for (int o = 16; o > 0; o >>= 1)
        s += __shfl_xor_sync(0xFFFFFFFFu, s, o);
    if (lane == 0) *dst = s;
}

// ---------------------------------------------------------------------------
// Kernel 2: fused distance-GEMM + argmin + gather.
// Each block owns BM=128 rows of x, loops over all K codewords in BN=128
// tiles, keeps a running (min, argmin) per row, then gathers codebook rows.
// Output layout: out[0 .. N*DIM) = quantized, out[N*DIM .. N*DIM+N) = indices
// (as float values).
// ---------------------------------------------------------------------------
__global__ __launch_bounds__(NTHREADS, 2)
void vq_argmin_kernel(const float* __restrict__ x,
                      const float* __restrict__ cb,
                      float* __restrict__ out) {
    __shared__ float As[BK][BM];     // A tile, transposed: [k][m]
    __shared__ float Bs[BK][BN];     // B tile, transposed: [k][n]
    __shared__ float red_val[BM][16];
    __shared__ int   red_idx[BM][16];

    const int tid = threadIdx.x;
    const int tx = tid & 15;         // column-group 0..15 (owns cols tx*8..+7)
    const int ty = tid >> 4;         // row-group    0..15 (owns rows ty*8..+7)
    const int rowbase = blockIdx.x * BM;

    // Per-thread x^2 for its 8 rows (constant across all codeword tiles)
    float xsq_r[TM];
#pragma unroll
    for (int i = 0; i < TM; i++)
        xsq_r[i] = g_xsq[rowbase + ty * TM + i];

    float bestv[TM];
    int   besti[TM];
#pragma unroll
    for (int i = 0; i < TM; i++) { bestv[i] = 3.4e38f; besti[i] = 0; }

    for (int nb = 0; nb < KCB; nb += BN) {
        float acc[TM][TN];
#pragma unroll
        for (int i = 0; i < TM; i++)
#pragma unroll
            for (int j = 0; j < TN; j++) acc[i][j] = 0.f;

        for (int kb = 0; kb < DIM; kb += BK) {
            // Stage tiles: 128 rows x 16 dims each = 512 float4 per tile,
            // 2 float4 per thread per tile, transposed into [k][m] layout.
#pragma unroll
            for (int i = 0; i < 2; i++) {
                int idx = tid * 2 + i;          // 0..511
                int m  = idx >> 2;              // row within tile
                int k4 = (idx & 3) * 4;         // dim quad within BK
                float4 a = *(const float4*)(x  + (size_t)(rowbase + m) * DIM + kb + k4);
                As[k4 + 0][m] = a.x; As[k4 + 1][m] = a.y;
                As[k4 + 2][m] = a.z; As[k4 + 3][m] = a.w;
                float4 b = *(const float4*)(cb + (size_t)(nb + m) * DIM + kb + k4);
                Bs[k4 + 0][m] = b.x; Bs[k4 + 1][m] = b.y;
                Bs[k4 + 2][m] = b.z; Bs[k4 + 3][m] = b.w;
            }
            __syncthreads();

#pragma unroll
            for (int k = 0; k < BK; k++) {
                float a[TM], b[TN];
                *(float4*)(a)     = *(const float4*)&As[k][ty * TM];
                *(float4*)(a + 4) = *(const float4*)&As[k][ty * TM + 4];
                *(float4*)(b)     = *(const float4*)&Bs[k][tx * TN];
                *(float4*)(b + 4) = *(const float4*)&Bs[k][tx * TN + 4];
#pragma unroll
                for (int i = 0; i < TM; i++)
#pragma unroll
                    for (int j = 0; j < TN; j++)
                        acc[i][j] = fmaf(a[i], b[j], acc[i][j]);
            }
            __syncthreads();
        }

        // Epilogue: dist = (x^2 - 2*dot) + c^2 (mirrors reference rounding
        // order: 2*dot is exact, fmaf(-2,dot,x2) == rn(x2 - 2*dot), then a
        // separate rounded add of c^2). Strict < keeps the earliest index.
#pragma unroll
        for (int j = 0; j < TN; j++) {
            int n = nb + tx * TN + j;
            float cs = g_csq[n];
#pragma unroll
            for (int i = 0; i < TM; i++) {
                float s = fmaf(-2.f, acc[i][j], xsq_r[i]) + cs;
                if (s < bestv[i]) { bestv[i] = s; besti[i] = n; }
            }
        }
    }

    // Cross-thread reduction: 16 column-group threads per row.
#pragma unroll
    for (int i = 0; i < TM; i++) {
        red_val[ty * TM + i][tx] = bestv[i];
        red_idx[ty * TM + i][tx] = besti[i];
    }
    __syncthreads();

    if (tid < BM) {
        float bv = red_val[tid][0];
        int   bi = red_idx[tid][0];
#pragma unroll
        for (int t = 1; t < 16; t++) {
            float v = red_val[tid][t];
            int   id = red_idx[tid][t];
            // smaller index wins ties (jnp.argmin returns first occurrence)
            if (v < bv || (v == bv && id < bi)) { bv = v; bi = id; }
        }
        red_idx[tid][0] = bi;
        out[(size_t)NPTS * DIM + rowbase + tid] = (float)bi;
    }
    __syncthreads();

    // Gather: 2 threads per row, 32 float4 each (256 floats per row).
    {
        int r = tid >> 1;
        int h = tid & 1;
        int idx = red_idx[r][0];
        const float4* src = (const float4*)(cb + (size_t)idx * DIM) + h * 32;
        float4* dst = (float4*)(out + (size_t)(rowbase + r) * DIM) + h * 32;
#pragma unroll
        for (int i = 0; i < 32; i++) dst[i] = src[i];
    }
}

// ---------------------------------------------------------------------------
extern "C" void kernel_launch(void* const* d_in, const int* in_sizes, int n_in,
                              void* d_out, int out_size) {
    const float* x  = (const float*)d_in[0];   // (65536, 256) f32
    const float* cb = (const float*)d_in[1];   // (4096, 256)  f32
    float* out = (float*)d_out;

    // One warp per row: 65536 + 4096 = 69632 warps
    int warps = NPTS + KCB;
    int blocks = (warps * 32 + 255) / 256;
    sqnorm_kernel<<<blocks, 256>>>(x, cb);

    vq_argmin_kernel<<<NPTS / BM, NTHREADS>>>(x, cb, out);
}